// round 2
// baseline (speedup 1.0000x reference)
#include <cuda_runtime.h>
#include <cstdint>

#define Bsz  128
#define Tlen 1024
#define Isz  512
#define Hsz  512
#define Gsz  2048     // 4H
#define NCTA 128
#define TPB  256
#define ZC   16       // z-columns per CTA (4 gates x 4 h-cols)
#define HC   4        // h-columns per CTA
#define KT   64       // k-tile depth
#define KTOT 1024     // I + H
#define NKT  16       // KTOT / KT

// Scratch (__device__ globals; no runtime allocation)
__device__ float g_xT[(size_t)Tlen * Isz * Bsz];   // [t][k][b], 256 MiB
__device__ float g_hbuf[2 * Hsz * Bsz];            // [buf][col][b], double buffered
__device__ volatile unsigned g_flags[NCTA];
__device__ volatile unsigned g_release;

// ---------------- init: reset barrier state + h0 = 0 ----------------
__global__ void init_kernel() {
    int idx = blockIdx.x * blockDim.x + threadIdx.x;
    int stride = gridDim.x * blockDim.x;
    for (int i = idx; i < 2 * Hsz * Bsz; i += stride) g_hbuf[i] = 0.f;
    if (idx < NCTA) g_flags[idx] = 0u;
    if (idx == 0)   g_release   = 0u;
}

// ---------------- transpose x[b][t][i] -> xT[t][k][b] ----------------
__global__ void transpose_x(const float* __restrict__ x) {
    __shared__ float tile[32][129];
    int t  = blockIdx.x;
    int kc = blockIdx.y;                    // 16 chunks of 32 k
    int tid = threadIdx.x;
    for (int i = tid; i < 32 * 128; i += TPB) {
        int b  = i >> 5;
        int kk = i & 31;
        tile[kk][b] = x[(size_t)b * (Tlen * Isz) + (size_t)t * Isz + kc * 32 + kk];
    }
    __syncthreads();
    for (int i = tid; i < 32 * 128; i += TPB) {
        int kk = i >> 7;
        int b  = i & 127;
        g_xT[(size_t)t * (Isz * Bsz) + (size_t)(kc * 32 + kk) * Bsz + b] = tile[kk][b];
    }
}

// ---------------- helpers ----------------
__device__ __forceinline__ void cp_async16(float* dst, const float* src) {
    uint32_t sa = (uint32_t)__cvta_generic_to_shared(dst);
    asm volatile("cp.async.cg.shared.global [%0], [%1], 16;\n" :: "r"(sa), "l"(src));
}
__device__ __forceinline__ float sigmoidf_(float x) {
    return 1.f / (1.f + expf(-x));
}

// ---------------- persistent fused LSTM ----------------
__global__ void __launch_bounds__(TPB, 1) lstm_kernel(
    const float* __restrict__ Wk,    // [512][2048]
    const float* __restrict__ Rk,    // [512][2048]
    const float* __restrict__ bias,  // [2048]
    float* __restrict__ out)         // [B][T][H]
{
    extern __shared__ float sm[];
    float* ws = sm;                         // [1024][16]  weight slice (W over R)
    float* ub = ws + KTOT * ZC;             // [2][64][128] u staging
    float* zb = ub + 2 * KT * Bsz;          // [16][128]   z exchange
    float* cs = zb + ZC * Bsz;              // [4][128]    cell state (this CTA's cols)
    float* bs = cs + HC * Bsz;              // [16]        bias slice

    const int tid = threadIdx.x;
    const int cta = blockIdx.x;

    // weight slice: ws[k][c], c = g*4 + hh  ->  global col g*512 + cta*4 + hh
    for (int i = tid; i < KTOT * ZC; i += TPB) {
        int k = i >> 4, c = i & 15;
        int G = (c >> 2) * Hsz + cta * HC + (c & 3);
        ws[i] = (k < Isz) ? Wk[(size_t)k * Gsz + G]
                          : Rk[(size_t)(k - Isz) * Gsz + G];
    }
    if (tid < ZC)
        bs[tid] = bias[(tid >> 2) * Hsz + cta * HC + (tid & 3)];
    for (int i = tid; i < HC * Bsz; i += TPB) cs[i] = 0.f;
    __syncthreads();

    const int bp2 = (tid >> 2) * 2;     // 2 consecutive batch rows
    const int g4  = (tid & 3) * 4;      // 4 consecutive z-cols (one gate)

    for (int t = 0; t < Tlen; t++) {
        // prefetch k-tile 0 (x part)
        {
            const float* src = g_xT + (size_t)t * (Isz * Bsz);
            #pragma unroll
            for (int j = 0; j < 8; j++) {
                int idx = tid + TPB * j;
                cp_async16(ub + idx * 4, src + idx * 4);
            }
            asm volatile("cp.async.commit_group;\n");
        }

        float2 acc[4];
        #pragma unroll
        for (int j = 0; j < 4; j++) acc[j] = make_float2(0.f, 0.f);

        for (int kt = 0; kt < NKT; kt++) {
            if (kt < NKT - 1) {
                int k0 = (kt + 1) * KT;
                const float* src = (k0 < Isz)
                    ? (g_xT   + (size_t)t * (Isz * Bsz) + (size_t)k0 * Bsz)
                    : (g_hbuf + (size_t)(t & 1) * (Hsz * Bsz) + (size_t)(k0 - Isz) * Bsz);
                float* dst = ub + ((kt + 1) & 1) * (KT * Bsz);
                #pragma unroll
                for (int j = 0; j < 8; j++) {
                    int idx = tid + TPB * j;
                    cp_async16(dst + idx * 4, src + idx * 4);
                }
                asm volatile("cp.async.commit_group;\n");
                asm volatile("cp.async.wait_group 1;\n");
            } else {
                asm volatile("cp.async.wait_group 0;\n");
            }
            __syncthreads();

            const float* U = ub + (kt & 1) * (KT * Bsz);
            const float* W = ws + kt * KT * ZC;
            #pragma unroll 8
            for (int kk = 0; kk < KT; kk++) {
                float2 a = *(const float2*)(U + kk * Bsz + bp2);
                float4 w = *(const float4*)(W + kk * ZC + g4);
                acc[0].x += a.x * w.x;  acc[0].y += a.y * w.x;
                acc[1].x += a.x * w.y;  acc[1].y += a.y * w.y;
                acc[2].x += a.x * w.z;  acc[2].y += a.y * w.z;
                acc[3].x += a.x * w.w;  acc[3].y += a.y * w.w;
            }
            __syncthreads();
        }

        // exchange z through smem (gate columns live in different threads)
        #pragma unroll
        for (int j = 0; j < 4; j++) {
            float bv = bs[g4 + j];
            *(float2*)(zb + (g4 + j) * Bsz + bp2) =
                make_float2(acc[j].x + bv, acc[j].y + bv);
        }
        __syncthreads();

        // gates + state update (faithful quirk: c carried forward tanh'd)
        for (int it = tid; it < HC * Bsz; it += TPB) {
            int hh = it >> 7, b = it & 127;
            float zi = zb[(0  + hh) * Bsz + b];
            float zf = zb[(4  + hh) * Bsz + b];
            float zg = zb[(8  + hh) * Bsz + b];
            float zo = zb[(12 + hh) * Bsz + b];
            float ii = sigmoidf_(zi);
            float ff = sigmoidf_(zf);
            float gg = tanhf(zg);
            float oo = sigmoidf_(zo);
            float cn = tanhf(ff * cs[it] + ii * gg);
            float hn = oo * cn;
            cs[it] = cn;
            g_hbuf[(size_t)((t + 1) & 1) * (Hsz * Bsz)
                   + (size_t)(cta * HC + hh) * Bsz + b] = hn;
            out[(size_t)b * (Tlen * Hsz) + (size_t)t * Hsz + cta * HC + hh] = hn;
        }

        // grid barrier (flag array + single poller; all 128 CTAs co-resident)
        if (t < Tlen - 1) {
            __threadfence();
            __syncthreads();
            unsigned gen = (unsigned)(t + 1);
            if (cta == 0) {
                if (tid == 0) g_flags[0] = gen;
                __syncthreads();
                if (tid < 32) {
                    bool done;
                    do {
                        done = true;
                        #pragma unroll
                        for (int j = 0; j < NCTA / 32; j++)
                            if (g_flags[tid + 32 * j] < gen) done = false;
                    } while (!__all_sync(0xffffffffu, done));
                    if (tid == 0) { __threadfence(); g_release = gen; }
                }
                __syncthreads();
            } else {
                if (tid == 0) {
                    g_flags[cta] = gen;
                    while (g_release < gen) { }
                    __threadfence();
                }
                __syncthreads();
            }
        }
    }
}

// ---------------- launch ----------------
extern "C" void kernel_launch(void* const* d_in, const int* in_sizes, int n_in,
                              void* d_out, int out_size) {
    const float* x    = (const float*)d_in[0];
    const float* Wk   = (const float*)d_in[1];
    const float* Rk   = (const float*)d_in[2];
    const float* bias = (const float*)d_in[3];
    float* out = (float*)d_out;

    const size_t smem_bytes =
        (size_t)(KTOT * ZC + 2 * KT * Bsz + ZC * Bsz + HC * Bsz + ZC) * sizeof(float);
    cudaFuncSetAttribute(lstm_kernel, cudaFuncAttributeMaxDynamicSharedMemorySize,
                         (int)smem_bytes);

    init_kernel<<<64, TPB>>>();
    transpose_x<<<dim3(Tlen, 16), TPB>>>(x);
    lstm_kernel<<<NCTA, TPB, smem_bytes>>>(Wk, Rk, bias, out);
}

// round 4
// speedup vs baseline: 1.4947x; 1.4947x over previous
#include <cuda_runtime.h>
#include <cuda_bf16.h>
#include <cstdint>

#define Bsz   128
#define Tlen  1024
#define Isz   512
#define Hsz   512
#define NCTA  128
#define TPB   256
#define NCG   64          // col-groups
#define KT    64          // k per tile
#define NKT   16

// ---------------- device scratch ----------------
__device__ __nv_bfloat16 g_x_hi[(size_t)Tlen * Bsz * Isz];   // [t][b][k]
__device__ __nv_bfloat16 g_x_lo[(size_t)Tlen * Bsz * Isz];
__device__ __nv_bfloat16 g_h_hi[2 * Bsz * Hsz];              // [par][b][k']
__device__ __nv_bfloat16 g_h_lo[2 * Bsz * Hsz];
__device__ __nv_bfloat16 g_w_hi[(size_t)2048 * 1024];        // [g][k]
__device__ __nv_bfloat16 g_w_lo[(size_t)2048 * 1024];
__device__ volatile unsigned g_flags[NCTA];
__device__ volatile unsigned g_release;

// ---------------- helpers ----------------
__device__ __forceinline__ uint32_t smem_u32(const void* p) {
    uint32_t a;
    asm("{ .reg .u64 t; cvta.to.shared.u64 t, %1; cvt.u32.u64 %0, t; }" : "=r"(a) : "l"(p));
    return a;
}
__device__ __forceinline__ void cpa16(uint32_t dst, const void* src) {
    asm volatile("cp.async.cg.shared.global [%0], [%1], 16;\n" :: "r"(dst), "l"(src));
}
#define CP_COMMIT()  asm volatile("cp.async.commit_group;\n")
#define CP_WAIT(n)   asm volatile("cp.async.wait_group %0;\n" :: "n"(n))

#define LDSM4(r, a) \
    asm volatile("ldmatrix.sync.aligned.m8n8.x4.shared.b16 {%0,%1,%2,%3},[%4];" \
        : "=r"((r)[0]),"=r"((r)[1]),"=r"((r)[2]),"=r"((r)[3]) : "r"(a))
#define LDSM2(r, a) \
    asm volatile("ldmatrix.sync.aligned.m8n8.x2.shared.b16 {%0,%1},[%2];" \
        : "=r"((r)[0]),"=r"((r)[1]) : "r"(a))
#define MMA16816(d, a, b) \
    asm volatile("mma.sync.aligned.m16n8k16.row.col.f32.bf16.bf16.f32 " \
        "{%0,%1,%2,%3},{%4,%5,%6,%7},{%8,%9},{%0,%1,%2,%3};" \
        : "+f"((d)[0]),"+f"((d)[1]),"+f"((d)[2]),"+f"((d)[3]) \
        : "r"((a)[0]),"r"((a)[1]),"r"((a)[2]),"r"((a)[3]),"r"((b)[0]),"r"((b)[1]))

__device__ __forceinline__ float sigmoidf_(float x) { return 1.f / (1.f + expf(-x)); }

// ---------------- smem layout (bytes) ----------------
// bs[32] floats        @ 0
// ws_hi [32][1032]bf16 @ 128     (66048 B)
// ws_lo                @ 66176   (66048 B)
// A bufs: 2 x { hi [64][72]bf16 (18432), lo (18432) } @ 132224
#define BS_OFF    0
#define WS_HI     128
#define WS_LO     66176
#define WS_STRIDE 2064          // 1032 bf16
#define A_OFF     132224
#define A_BUF     36864
#define A_LOH     18432
#define A_STRIDE  144           // 72 bf16
#define SMEM_TOTAL 205952

// ---------------- prologue kernels ----------------
__global__ void init_kernel() {
    int idx = blockIdx.x * blockDim.x + threadIdx.x;
    int stride = gridDim.x * blockDim.x;
    for (int i = idx; i < 2 * Bsz * Hsz; i += stride) {
        g_h_hi[i] = __float2bfloat16(0.f);
        g_h_lo[i] = __float2bfloat16(0.f);
    }
    if (idx < NCTA) g_flags[idx] = 0u;
    if (idx == 0)   g_release   = 0u;
}

__global__ void prep_w(const float* __restrict__ Wk, const float* __restrict__ Rk) {
    __shared__ float tile[32][33];
    int gt = blockIdx.x * 32, kt = blockIdx.y * 32;
    int tid = threadIdx.x;
    for (int i = tid; i < 1024; i += TPB) {
        int kk = i >> 5, gg = i & 31;
        int k = kt + kk, g = gt + gg;
        tile[kk][gg] = (k < 512) ? Wk[(size_t)k * 2048 + g]
                                 : Rk[(size_t)(k - 512) * 2048 + g];
    }
    __syncthreads();
    for (int i = tid; i < 1024; i += TPB) {
        int gg = i >> 5, kk = i & 31;
        float v = tile[kk][gg];
        __nv_bfloat16 hi = __float2bfloat16(v);
        __nv_bfloat16 lo = __float2bfloat16(v - __bfloat162float(hi));
        size_t o = (size_t)(gt + gg) * 1024 + (size_t)(kt + kk);
        g_w_hi[o] = hi; g_w_lo[o] = lo;
    }
}

__global__ void prep_x(const float* __restrict__ x) {
    int t = blockIdx.x, b = blockIdx.y;
    const float* src = x + ((size_t)b * Tlen + t) * Isz;
    size_t o = ((size_t)t * Bsz + b) * Isz;
    for (int k = threadIdx.x; k < Isz; k += blockDim.x) {
        float v = src[k];
        __nv_bfloat16 hi = __float2bfloat16(v);
        g_x_hi[o + k] = hi;
        g_x_lo[o + k] = __float2bfloat16(v - __bfloat162float(hi));
    }
}

// ---------------- main persistent kernel ----------------
__global__ void __launch_bounds__(TPB, 1) lstm_mma(const float* __restrict__ bias,
                                                   float* __restrict__ out) {
    extern __shared__ char smem[];
    const uint32_t sbase = smem_u32(smem);
    float* bs = (float*)(smem + BS_OFF);

    const int tid = threadIdx.x, wid = tid >> 5, lid = tid & 31;
    const int cta = blockIdx.x;
    const int cg  = cta & 63;        // col-group (8 h-cols)
    const int bg  = cta >> 6;        // batch-group (64 rows)
    const int mwarp = wid & 3, nwarp = wid >> 2;

    // ---- load resident weight slice: ws row c=(hc*4+gate) <- g_w[gate*512+cg*8+hc]
    for (int i = tid; i < 32 * 128 * 2; i += TPB) {   // 32 rows x 128 chunks x 2 halves
        int half = i >= 32 * 128;
        int j = half ? i - 32 * 128 : i;
        int c = j >> 7, ch = j & 127;
        int g = (c & 3) * 512 + cg * 8 + (c >> 2);
        const __nv_bfloat16* src = (half ? g_w_lo : g_w_hi) + (size_t)g * 1024 + ch * 8;
        cpa16(sbase + (half ? WS_LO : WS_HI) + c * WS_STRIDE + ch * 16, src);
    }
    CP_COMMIT();
    if (tid < 32)
        bs[tid] = bias[(tid & 3) * 512 + cg * 8 + (tid >> 2)];
    CP_WAIT(0);
    __syncthreads();

    // ---- per-thread fragment addresses
    const uint32_t a_row = (mwarp * 16 + (lid & 15)) * A_STRIDE + (lid >> 4) * 16;
    uint32_t bAddr[2][2];   // [half][ntile]
    #pragma unroll
    for (int h = 0; h < 2; h++)
        #pragma unroll
        for (int nt = 0; nt < 2; nt++)
            bAddr[h][nt] = sbase + (h ? WS_LO : WS_HI)
                         + (nwarp * 16 + nt * 8 + (lid & 7)) * WS_STRIDE
                         + ((lid >> 3) & 1) * 16;

    float creg[2][2] = {{0.f, 0.f}, {0.f, 0.f}};   // [ntile][row r / r+8] (even lanes)

    auto load_tile = [&](int t, int kt, int p) {
        const int k0 = kt * KT;
        const uint32_t abuf = sbase + A_OFF + p * A_BUF;
        #pragma unroll
        for (int i = tid; i < 1024; i += TPB) {
            int half = i >> 9, r = (i >> 3) & 63, j = i & 7;
            const __nv_bfloat16* src;
            if (k0 < Isz)
                src = (half ? g_x_lo : g_x_hi)
                    + ((size_t)t * Bsz + bg * 64 + r) * Isz + k0 + j * 8;
            else
                src = (half ? g_h_lo : g_h_hi)
                    + ((size_t)(t & 1) * Bsz + bg * 64 + r) * Hsz + (k0 - Isz) + j * 8;
            cpa16(abuf + half * A_LOH + r * A_STRIDE + j * 16, src);
        }
        CP_COMMIT();
    };

    for (int t = 0; t < Tlen; t++) {
        float acc[2][4];
        #pragma unroll
        for (int nt = 0; nt < 2; nt++)
            #pragma unroll
            for (int j = 0; j < 4; j++) acc[nt][j] = 0.f;

        load_tile(t, 0, 0);

        for (int kt = 0; kt < NKT; kt++) {
            const int p = kt & 1;
            if (kt < NKT - 1) { load_tile(t, kt + 1, p ^ 1); CP_WAIT(1); }
            else              { CP_WAIT(0); }
            __syncthreads();

            const uint32_t ah_base = sbase + A_OFF + p * A_BUF + a_row;
            const uint32_t al_base = ah_base + A_LOH;
            #pragma unroll
            for (int ks = 0; ks < 4; ks++) {
                uint32_t ah[4], al[4];
                LDSM4(ah, ah_base + ks * 32);
                LDSM4(al, al_base + ks * 32);
                const uint32_t koff = kt * 128 + ks * 32;
                #pragma unroll
                for (int nt = 0; nt < 2; nt++) {
                    uint32_t bh[2], bl[2];
                    LDSM2(bh, bAddr[0][nt] + koff);
                    LDSM2(bl, bAddr[1][nt] + koff);
                    MMA16816(acc[nt], ah, bh);
                    MMA16816(acc[nt], ah, bl);
                    MMA16816(acc[nt], al, bh);
                }
            }
            __syncthreads();
        }

        // ---- epilogue: bias, lane-pair exchange, gates, state update
        const int q = lid & 3;
        const int par2 = (t + 1) & 1;
        #pragma unroll
        for (int nt = 0; nt < 2; nt++) {
            const int s0 = nwarp * 16 + nt * 8 + q * 2;
            float d0 = acc[nt][0] + bs[s0];
            float d1 = acc[nt][1] + bs[s0 + 1];
            float d2 = acc[nt][2] + bs[s0];
            float d3 = acc[nt][3] + bs[s0 + 1];
            float e0 = __shfl_xor_sync(0xffffffffu, d0, 1);
            float e1 = __shfl_xor_sync(0xffffffffu, d1, 1);
            float e2 = __shfl_xor_sync(0xffffffffu, d2, 1);
            float e3 = __shfl_xor_sync(0xffffffffu, d3, 1);
            if (!(q & 1)) {
                // rows r, r+8: z_i = d0/d2, z_f = d1/d3, z_g = e0/e2, z_o = e1/e3
                float i0 = sigmoidf_(d0), f0 = sigmoidf_(d1);
                float g0 = tanhf(e0),     o0 = sigmoidf_(e1);
                float c0 = tanhf(f0 * creg[nt][0] + i0 * g0);
                float h0 = o0 * c0;  creg[nt][0] = c0;

                float i1 = sigmoidf_(d2), f1 = sigmoidf_(d3);
                float g1 = tanhf(e2),     o1 = sigmoidf_(e3);
                float c1 = tanhf(f1 * creg[nt][1] + i1 * g1);
                float h1 = o1 * c1;  creg[nt][1] = c1;

                const int r    = lid >> 2;
                const int b0i  = bg * 64 + mwarp * 16 + r;
                const int hcol = cg * 8 + nwarp * 4 + nt * 2 + (q >> 1);
                out[(size_t)b0i * (Tlen * Hsz) + (size_t)t * Hsz + hcol] = h0;
                out[(size_t)(b0i + 8) * (Tlen * Hsz) + (size_t)t * Hsz + hcol] = h1;

                __nv_bfloat16 hh0 = __float2bfloat16(h0);
                __nv_bfloat16 hh1 = __float2bfloat16(h1);
                size_t hb = (size_t)par2 * Bsz * Hsz;
                g_h_hi[hb + (size_t)b0i * Hsz + hcol] = hh0;
                g_h_lo[hb + (size_t)b0i * Hsz + hcol] =
                    __float2bfloat16(h0 - __bfloat162float(hh0));
                g_h_hi[hb + (size_t)(b0i + 8) * Hsz + hcol] = hh1;
                g_h_lo[hb + (size_t)(b0i + 8) * Hsz + hcol] =
                    __float2bfloat16(h1 - __bfloat162float(hh1));
            }
        }

        // ---- grid barrier ----
        if (t < Tlen - 1) {
            __threadfence();
            __syncthreads();
            unsigned gen = (unsigned)(t + 1);
            if (cta == 0) {
                if (tid == 0) g_flags[0] = gen;
                __syncthreads();
                if (tid < 32) {
                    bool done;
                    do {
                        done = true;
                        #pragma unroll
                        for (int j = 0; j < NCTA / 32; j++)
                            if (g_flags[tid + 32 * j] < gen) done = false;
                    } while (!__all_sync(0xffffffffu, done));
                    if (tid == 0) { __threadfence(); g_release = gen; }
                }
                __syncthreads();
            } else {
                if (tid == 0) {
                    g_flags[cta] = gen;
                    while (g_release < gen) { }
                    __threadfence();
                }
                __syncthreads();
            }
        }
    }
}

// ---------------- launch ----------------
extern "C" void kernel_launch(void* const* d_in, const int* in_sizes, int n_in,
                              void* d_out, int out_size) {
    const float* x    = (const float*)d_in[0];
    const float* Wk   = (const float*)d_in[1];
    const float* Rk   = (const float*)d_in[2];
    const float* bias = (const float*)d_in[3];
    float* out = (float*)d_out;

    cudaFuncSetAttribute(lstm_mma, cudaFuncAttributeMaxDynamicSharedMemorySize, SMEM_TOTAL);

    init_kernel<<<64, TPB>>>();
    prep_w<<<dim3(64, 32), TPB>>>(Wk, Rk);
    prep_x<<<dim3(Tlen, Bsz), 128>>>(x);
    lstm_mma<<<NCTA, TPB, SMEM_TOTAL>>>(bias, out);
}

// round 5
// speedup vs baseline: 2.7582x; 1.8453x over previous
#include <cuda_runtime.h>
#include <cuda_bf16.h>
#include <cstdint>

#define Bsz   128
#define Tlen  1024
#define Isz   512
#define Hsz   512
#define NCTA  128
#define TPB   256
#define KT    64
#define NKT   16

// ---------------- device scratch ----------------
// x tiles: [t][bg(2)][kt(8)][8KB swizzled tile of 64 rows x 64 k bf16]
__device__ __align__(1024) char g_xs_hi[(size_t)Tlen * 2 * 8 * 8192];
__device__ __align__(1024) char g_xs_lo[(size_t)Tlen * 2 * 8 * 8192];
// h tiles: [par(2)][bg(2)][kt2(8)][8KB tile]
__device__ __align__(1024) char g_hs_hi[2 * 2 * 8 * 8192];
__device__ __align__(1024) char g_hs_lo[2 * 2 * 8 * 8192];
__device__ __nv_bfloat16 g_w_hi[(size_t)2048 * 1024];        // [g][k]
__device__ __nv_bfloat16 g_w_lo[(size_t)2048 * 1024];
__device__ volatile unsigned g_flags[NCTA];
__device__ volatile unsigned g_release;

// ---------------- helpers ----------------
__device__ __forceinline__ uint32_t smem_u32(const void* p) {
    uint32_t a;
    asm("{ .reg .u64 t; cvta.to.shared.u64 t, %1; cvt.u32.u64 %0, t; }" : "=r"(a) : "l"(p));
    return a;
}
__device__ __forceinline__ void cpa16(uint32_t dst, const void* src) {
    asm volatile("cp.async.cg.shared.global [%0], [%1], 16;\n" :: "r"(dst), "l"(src));
}
#define CP_COMMIT()  asm volatile("cp.async.commit_group;\n")
#define CP_WAIT(n)   asm volatile("cp.async.wait_group %0;\n" :: "n"(n))

__device__ __forceinline__ void bulk_ld(uint32_t dst, const void* src, uint32_t bytes,
                                        uint32_t mbar) {
    asm volatile(
        "cp.async.bulk.shared::cluster.global.mbarrier::complete_tx::bytes [%0], [%1], %2, [%3];"
        :: "r"(dst), "l"(src), "r"(bytes), "r"(mbar) : "memory");
}
__device__ __forceinline__ void mbar_init(uint32_t m, uint32_t cnt) {
    asm volatile("mbarrier.init.shared.b64 [%0], %1;" :: "r"(m), "r"(cnt) : "memory");
}
__device__ __forceinline__ void mbar_expect(uint32_t m, uint32_t bytes) {
    asm volatile("mbarrier.arrive.expect_tx.shared.b64 _, [%0], %1;"
                 :: "r"(m), "r"(bytes) : "memory");
}
__device__ __forceinline__ void mbar_wait(uint32_t m, uint32_t parity) {
    uint32_t done;
    asm volatile("{\n\t.reg .pred p;\n\t"
        "mbarrier.try_wait.parity.acquire.cta.shared::cta.b64 p, [%1], %2;\n\t"
        "selp.b32 %0, 1, 0, p;\n\t}"
        : "=r"(done) : "r"(m), "r"(parity) : "memory");
    if (!done) {
        asm volatile("{\n\t.reg .pred P1;\n\t"
            "WL_%=:\n\t"
            "mbarrier.try_wait.parity.acquire.cta.shared::cta.b64 P1, [%0], %1, 0x989680;\n\t"
            "@P1 bra.uni WD_%=;\n\t"
            "bra.uni WL_%=;\n\t"
            "WD_%=:\n\t}" :: "r"(m), "r"(parity) : "memory");
    }
}

#define LDSM4(r, a) \
    asm volatile("ldmatrix.sync.aligned.m8n8.x4.shared.b16 {%0,%1,%2,%3},[%4];" \
        : "=r"((r)[0]),"=r"((r)[1]),"=r"((r)[2]),"=r"((r)[3]) : "r"(a))
#define LDSM2(r, a) \
    asm volatile("ldmatrix.sync.aligned.m8n8.x2.shared.b16 {%0,%1},[%2];" \
        : "=r"((r)[0]),"=r"((r)[1]) : "r"(a))
#define MMA16816(d, a, b) \
    asm volatile("mma.sync.aligned.m16n8k16.row.col.f32.bf16.bf16.f32 " \
        "{%0,%1,%2,%3},{%4,%5,%6,%7},{%8,%9},{%0,%1,%2,%3};" \
        : "+f"((d)[0]),"+f"((d)[1]),"+f"((d)[2]),"+f"((d)[3]) \
        : "r"((a)[0]),"r"((a)[1]),"r"((a)[2]),"r"((a)[3]),"r"((b)[0]),"r"((b)[1]))

__device__ __forceinline__ float sigmoidf_(float x) { return 1.f / (1.f + expf(-x)); }

// ---------------- smem layout (bytes) ----------------
#define BS_OFF     0
#define MB_OFF     128
#define WS_HI      1024
#define WS_LO      67072
#define WS_STRIDE  2064
#define A_OFF      133120
#define A_BUF      16384
#define A_LOH      8192
#define SMEM_TOTAL 165888

// ---------------- prologue kernels ----------------
__global__ void init_kernel() {
    int idx = blockIdx.x * blockDim.x + threadIdx.x;
    int stride = gridDim.x * blockDim.x;
    int* hh = (int*)g_hs_hi;
    int* hl = (int*)g_hs_lo;
    for (int i = idx; i < (2 * 2 * 8 * 8192) / 4; i += stride) { hh[i] = 0; hl[i] = 0; }
    if (idx < NCTA) g_flags[idx] = 0u;
    if (idx == 0)   g_release   = 0u;
}

__global__ void prep_w(const float* __restrict__ Wk, const float* __restrict__ Rk) {
    __shared__ float tile[32][33];
    int gt = blockIdx.x * 32, kt = blockIdx.y * 32;
    int tid = threadIdx.x;
    for (int i = tid; i < 1024; i += TPB) {
        int kk = i >> 5, gg = i & 31;
        int k = kt + kk, g = gt + gg;
        tile[kk][gg] = (k < 512) ? Wk[(size_t)k * 2048 + g]
                                 : Rk[(size_t)(k - 512) * 2048 + g];
    }
    __syncthreads();
    for (int i = tid; i < 1024; i += TPB) {
        int gg = i >> 5, kk = i & 31;
        float v = tile[kk][gg];
        __nv_bfloat16 hi = __float2bfloat16(v);
        __nv_bfloat16 lo = __float2bfloat16(v - __bfloat162float(hi));
        size_t o = (size_t)(gt + gg) * 1024 + (size_t)(kt + kk);
        g_w_hi[o] = hi; g_w_lo[o] = lo;
    }
}

// x[b][t][k] -> swizzled tiles
__global__ void prep_x(const float* __restrict__ x) {
    int t = blockIdx.x, b = blockIdx.y;
    int bg = b >> 6, r = b & 63;
    const float* src = x + ((size_t)b * Tlen + t) * Isz;
    size_t tbase = (((size_t)t * 2 + bg) * 8) * 8192;
    for (int k = threadIdx.x; k < Isz; k += blockDim.x) {
        float v = src[k];
        __nv_bfloat16 hi = __float2bfloat16(v);
        __nv_bfloat16 lo = __float2bfloat16(v - __bfloat162float(hi));
        int kt = k >> 6, kk = k & 63;
        size_t off = tbase + (size_t)kt * 8192 + r * 128 + (((kk * 2) ^ ((r & 7) << 4)));
        *(__nv_bfloat16*)(g_xs_hi + off) = hi;
        *(__nv_bfloat16*)(g_xs_lo + off) = lo;
    }
}

// ---------------- main persistent kernel ----------------
__global__ void __launch_bounds__(TPB, 1) lstm_mma(const float* __restrict__ bias,
                                                   float* __restrict__ out) {
    extern __shared__ char smem[];
    const uint32_t sbase = smem_u32(smem);
    float* bs = (float*)(smem + BS_OFF);
    const uint32_t mb[2] = { sbase + MB_OFF, sbase + MB_OFF + 8 };

    const int tid = threadIdx.x, wid = tid >> 5, lid = tid & 31;
    const int cta = blockIdx.x;
    const int cg  = cta & 63;
    const int bg  = cta >> 6;
    const int mwarp = wid & 3, nwarp = wid >> 2;

    // resident weight slice (one-time)
    for (int i = tid; i < 32 * 128 * 2; i += TPB) {
        int half = i >= 32 * 128;
        int j = half ? i - 32 * 128 : i;
        int c = j >> 7, ch = j & 127;
        int g = (c & 3) * 512 + cg * 8 + (c >> 2);
        const __nv_bfloat16* src = (half ? g_w_lo : g_w_hi) + (size_t)g * 1024 + ch * 8;
        cpa16(sbase + (half ? WS_LO : WS_HI) + c * WS_STRIDE + ch * 16, src);
    }
    CP_COMMIT();
    if (tid < 32)
        bs[tid] = bias[(tid & 3) * 512 + cg * 8 + (tid >> 2)];
    if (tid == 0) { mbar_init(mb[0], 1); mbar_init(mb[1], 1); }
    CP_WAIT(0);
    __syncthreads();

    // per-thread fragment addressing
    const int rr = mwarp * 16 + (lid & 15);
    const uint32_t a_base  = rr * 128;
    const uint32_t a_cmask = (rr & 7) << 4;
    const uint32_t a_chi   = (lid >> 4) * 16;
    uint32_t bAddr[2][2];
    #pragma unroll
    for (int h = 0; h < 2; h++)
        #pragma unroll
        for (int nt = 0; nt < 2; nt++)
            bAddr[h][nt] = sbase + (h ? WS_LO : WS_HI)
                         + (nwarp * 16 + nt * 8 + (lid & 7)) * WS_STRIDE
                         + ((lid >> 3) & 1) * 16;

    float creg[2][2] = {{0.f, 0.f}, {0.f, 0.f}};
    int phase[2] = {0, 0};

    auto issue_tile = [&](int t, int kt, int p) {   // tid==0 only
        const char *sh, *sl;
        if (kt < 8) {
            size_t o = (((size_t)t * 2 + bg) * 8 + kt) * 8192;
            sh = g_xs_hi + o; sl = g_xs_lo + o;
        } else {
            size_t o = (((size_t)(t & 1) * 2 + bg) * 8 + (kt - 8)) * 8192;
            sh = g_hs_hi + o; sl = g_hs_lo + o;
        }
        const uint32_t abuf = sbase + A_OFF + p * A_BUF;
        mbar_expect(mb[p], 16384);
        bulk_ld(abuf,          sh, 8192, mb[p]);
        bulk_ld(abuf + A_LOH,  sl, 8192, mb[p]);
    };

    // prime tiles 0,1 of step 0
    if (tid == 0) { issue_tile(0, 0, 0); issue_tile(0, 1, 1); }

    for (int t = 0; t < Tlen; t++) {
        float acc[2][4];
        #pragma unroll
        for (int nt = 0; nt < 2; nt++)
            #pragma unroll
            for (int j = 0; j < 4; j++) acc[nt][j] = 0.f;

        for (int kt = 0; kt < NKT; kt++) {
            const int p = kt & 1;
            mbar_wait(mb[p], phase[p]);
            phase[p] ^= 1;

            const uint32_t abuf = sbase + A_OFF + p * A_BUF;
            #pragma unroll
            for (int ks = 0; ks < 4; ks++) {
                uint32_t ah[4], al[4];
                const uint32_t col = ((uint32_t)(ks * 32) + a_chi) ^ a_cmask;
                LDSM4(ah, abuf + a_base + col);
                LDSM4(al, abuf + A_LOH + a_base + col);
                const uint32_t koff = kt * 128 + ks * 32;
                #pragma unroll
                for (int nt = 0; nt < 2; nt++) {
                    uint32_t bh[2], bl[2];
                    LDSM2(bh, bAddr[0][nt] + koff);
                    LDSM2(bl, bAddr[1][nt] + koff);
                    MMA16816(acc[nt], ah, bh);
                    MMA16816(acc[nt], ah, bl);
                    MMA16816(acc[nt], al, bh);
                }
            }
            __syncthreads();                       // buffer p consumed by all warps
            if (kt < NKT - 2 && tid == 0)
                issue_tile(t, kt + 2, p);
        }

        // ---- epilogue ----
        const int q = lid & 3;
        const int par2 = (t + 1) & 1;
        #pragma unroll
        for (int nt = 0; nt < 2; nt++) {
            const int s0 = nwarp * 16 + nt * 8 + q * 2;
            float d0 = acc[nt][0] + bs[s0];
            float d1 = acc[nt][1] + bs[s0 + 1];
            float d2 = acc[nt][2] + bs[s0];
            float d3 = acc[nt][3] + bs[s0 + 1];
            float e0 = __shfl_xor_sync(0xffffffffu, d0, 1);
            float e1 = __shfl_xor_sync(0xffffffffu, d1, 1);
            float e2 = __shfl_xor_sync(0xffffffffu, d2, 1);
            float e3 = __shfl_xor_sync(0xffffffffu, d3, 1);
            if (!(q & 1)) {
                float i0 = sigmoidf_(d0), f0 = sigmoidf_(d1);
                float g0 = tanhf(e0),     o0 = sigmoidf_(e1);
                float c0 = tanhf(f0 * creg[nt][0] + i0 * g0);
                float h0 = o0 * c0;  creg[nt][0] = c0;

                float i1 = sigmoidf_(d2), f1 = sigmoidf_(d3);
                float g1 = tanhf(e2),     o1 = sigmoidf_(e3);
                float c1 = tanhf(f1 * creg[nt][1] + i1 * g1);
                float h1 = o1 * c1;  creg[nt][1] = c1;

                const int r    = lid >> 2;
                const int b0i  = bg * 64 + mwarp * 16 + r;
                const int hcol = cg * 8 + nwarp * 4 + nt * 2 + (q >> 1);
                out[(size_t)b0i * (Tlen * Hsz) + (size_t)t * Hsz + hcol] = h0;
                out[(size_t)(b0i + 8) * (Tlen * Hsz) + (size_t)t * Hsz + hcol] = h1;

                const int kt2 = hcol >> 6, kk = hcol & 63;
                __nv_bfloat16 hh0 = __float2bfloat16(h0);
                __nv_bfloat16 hh1 = __float2bfloat16(h1);
                {
                    int r0 = b0i & 63, bgh = b0i >> 6;
                    size_t off = (((size_t)par2 * 2 + bgh) * 8 + kt2) * 8192
                               + r0 * 128 + (((kk * 2) ^ ((r0 & 7) << 4)));
                    *(__nv_bfloat16*)(g_hs_hi + off) = hh0;
                    *(__nv_bfloat16*)(g_hs_lo + off) =
                        __float2bfloat16(h0 - __bfloat162float(hh0));
                }
                {
                    int b1i = b0i + 8;
                    int r1 = b1i & 63, bgh = b1i >> 6;
                    size_t off = (((size_t)par2 * 2 + bgh) * 8 + kt2) * 8192
                               + r1 * 128 + (((kk * 2) ^ ((r1 & 7) << 4)));
                    *(__nv_bfloat16*)(g_hs_hi + off) = hh1;
                    *(__nv_bfloat16*)(g_hs_lo + off) =
                        __float2bfloat16(h1 - __bfloat162float(hh1));
                }
            }
        }

        // prefetch next step's x tiles (0,1) before the grid barrier
        if (t < Tlen - 1 && tid == 0) { issue_tile(t + 1, 0, 0); issue_tile(t + 1, 1, 1); }

        // ---- grid barrier ----
        if (t < Tlen - 1) {
            __threadfence();
            __syncthreads();
            unsigned gen = (unsigned)(t + 1);
            if (cta == 0) {
                if (tid == 0) g_flags[0] = gen;
                __syncthreads();
                if (tid < 32) {
                    bool done;
                    do {
                        done = true;
                        #pragma unroll
                        for (int j = 0; j < NCTA / 32; j++)
                            if (g_flags[tid + 32 * j] < gen) done = false;
                    } while (!__all_sync(0xffffffffu, done));
                    if (tid == 0) { __threadfence(); g_release = gen; }
                }
                __syncthreads();
            } else {
                if (tid == 0) {
                    g_flags[cta] = gen;
                    while (g_release < gen) { }
                    __threadfence();
                }
                __syncthreads();
            }
        }
    }
}

// ---------------- launch ----------------
extern "C" void kernel_launch(void* const* d_in, const int* in_sizes, int n_in,
                              void* d_out, int out_size) {
    const float* x    = (const float*)d_in[0];
    const float* Wk   = (const float*)d_in[1];
    const float* Rk   = (const float*)d_in[2];
    const float* bias = (const float*)d_in[3];
    float* out = (float*)d_out;

    cudaFuncSetAttribute(lstm_mma, cudaFuncAttributeMaxDynamicSharedMemorySize, SMEM_TOTAL);

    init_kernel<<<64, TPB>>>();
    prep_w<<<dim3(64, 32), TPB>>>(Wk, Rk);
    prep_x<<<dim3(Tlen, Bsz), 128>>>(x);
    lstm_mma<<<NCTA, TPB, SMEM_TOTAL>>>(bias, out);
}

// round 6
// speedup vs baseline: 4.0813x; 1.4797x over previous
#include <cuda_runtime.h>
#include <cuda_bf16.h>
#include <cstdint>

#define Bsz   128
#define Tlen  1024
#define Isz   512
#define Hsz   512
#define NCTA  128
#define TPB   288      // 8 compute warps + 1 producer warp
#define PTPB  256
#define NKT   16
#define NSTG  4

// ---------------- device scratch ----------------
__device__ __align__(1024) char g_xs_hi[(size_t)Tlen * 2 * 8 * 8192];
__device__ __align__(1024) char g_xs_lo[(size_t)Tlen * 2 * 8 * 8192];
__device__ __align__(1024) char g_hs_hi[2 * 2 * 8 * 8192];
__device__ __align__(1024) char g_hs_lo[2 * 2 * 8 * 8192];
__device__ __nv_bfloat16 g_w_hi[(size_t)2048 * 1024];
__device__ __nv_bfloat16 g_w_lo[(size_t)2048 * 1024];
__device__ volatile unsigned g_flags[NCTA];
__device__ volatile unsigned g_release;

// ---------------- helpers ----------------
__device__ __forceinline__ uint32_t smem_u32(const void* p) {
    uint32_t a;
    asm("{ .reg .u64 t; cvta.to.shared.u64 t, %1; cvt.u32.u64 %0, t; }" : "=r"(a) : "l"(p));
    return a;
}
__device__ __forceinline__ void cpa16(uint32_t dst, const void* src) {
    asm volatile("cp.async.cg.shared.global [%0], [%1], 16;\n" :: "r"(dst), "l"(src));
}
#define CP_COMMIT()  asm volatile("cp.async.commit_group;\n")
#define CP_WAIT(n)   asm volatile("cp.async.wait_group %0;\n" :: "n"(n))

__device__ __forceinline__ void bulk_ld(uint32_t dst, const void* src, uint32_t bytes,
                                        uint32_t mbar) {
    asm volatile(
        "cp.async.bulk.shared::cluster.global.mbarrier::complete_tx::bytes [%0], [%1], %2, [%3];"
        :: "r"(dst), "l"(src), "r"(bytes), "r"(mbar) : "memory");
}
__device__ __forceinline__ void mbar_init(uint32_t m, uint32_t cnt) {
    asm volatile("mbarrier.init.shared.b64 [%0], %1;" :: "r"(m), "r"(cnt) : "memory");
}
__device__ __forceinline__ void mbar_expect(uint32_t m, uint32_t bytes) {
    asm volatile("mbarrier.arrive.expect_tx.shared.b64 _, [%0], %1;"
                 :: "r"(m), "r"(bytes) : "memory");
}
__device__ __forceinline__ void mbar_arrive(uint32_t m) {
    asm volatile("mbarrier.arrive.shared.b64 _, [%0];" :: "r"(m) : "memory");
}
__device__ __forceinline__ void mbar_wait(uint32_t m, uint32_t parity) {
    uint32_t done;
    asm volatile("{\n\t.reg .pred p;\n\t"
        "mbarrier.try_wait.parity.acquire.cta.shared::cta.b64 p, [%1], %2;\n\t"
        "selp.b32 %0, 1, 0, p;\n\t}"
        : "=r"(done) : "r"(m), "r"(parity) : "memory");
    if (!done) {
        asm volatile("{\n\t.reg .pred P1;\n\t"
            "WL_%=:\n\t"
            "mbarrier.try_wait.parity.acquire.cta.shared::cta.b64 P1, [%0], %1, 0x989680;\n\t"
            "@P1 bra.uni WD_%=;\n\t"
            "bra.uni WL_%=;\n\t"
            "WD_%=:\n\t}" :: "r"(m), "r"(parity) : "memory");
    }
}

#define LDSM4(r, a) \
    asm volatile("ldmatrix.sync.aligned.m8n8.x4.shared.b16 {%0,%1,%2,%3},[%4];" \
        : "=r"((r)[0]),"=r"((r)[1]),"=r"((r)[2]),"=r"((r)[3]) : "r"(a))
#define LDSM2(r, a) \
    asm volatile("ldmatrix.sync.aligned.m8n8.x2.shared.b16 {%0,%1},[%2];" \
        : "=r"((r)[0]),"=r"((r)[1]) : "r"(a))
#define MMA16816(d, a, b) \
    asm volatile("mma.sync.aligned.m16n8k16.row.col.f32.bf16.bf16.f32 " \
        "{%0,%1,%2,%3},{%4,%5,%6,%7},{%8,%9},{%0,%1,%2,%3};" \
        : "+f"((d)[0]),"+f"((d)[1]),"+f"((d)[2]),"+f"((d)[3]) \
        : "r"((a)[0]),"r"((a)[1]),"r"((a)[2]),"r"((a)[3]),"r"((b)[0]),"r"((b)[1]))

__device__ __forceinline__ float sigmoidf_(float x) { return 1.f / (1.f + expf(-x)); }

// ---------------- smem layout (bytes) ----------------
#define BS_OFF     0
#define MB_FULL    128          // 4 x 8B
#define MB_EMPTY   192          // 4 x 8B
#define WS_HI      1024
#define WS_LO      67072
#define WS_STRIDE  2064
#define A_OFF      133120
#define A_BUF      16384
#define A_LOH      8192
#define SMEM_TOTAL (A_OFF + NSTG * A_BUF)   // 198656

// ---------------- prologue kernels ----------------
__global__ void init_kernel() {
    int idx = blockIdx.x * blockDim.x + threadIdx.x;
    int stride = gridDim.x * blockDim.x;
    int* hh = (int*)g_hs_hi;
    int* hl = (int*)g_hs_lo;
    for (int i = idx; i < (2 * 2 * 8 * 8192) / 4; i += stride) { hh[i] = 0; hl[i] = 0; }
    if (idx < NCTA) g_flags[idx] = 0u;
    if (idx == 0)   g_release   = 0u;
}

__global__ void prep_w(const float* __restrict__ Wk, const float* __restrict__ Rk) {
    __shared__ float tile[32][33];
    int gt = blockIdx.x * 32, kt = blockIdx.y * 32;
    int tid = threadIdx.x;
    for (int i = tid; i < 1024; i += PTPB) {
        int kk = i >> 5, gg = i & 31;
        int k = kt + kk, g = gt + gg;
        tile[kk][gg] = (k < 512) ? Wk[(size_t)k * 2048 + g]
                                 : Rk[(size_t)(k - 512) * 2048 + g];
    }
    __syncthreads();
    for (int i = tid; i < 1024; i += PTPB) {
        int gg = i >> 5, kk = i & 31;
        float v = tile[kk][gg];
        __nv_bfloat16 hi = __float2bfloat16(v);
        __nv_bfloat16 lo = __float2bfloat16(v - __bfloat162float(hi));
        size_t o = (size_t)(gt + gg) * 1024 + (size_t)(kt + kk);
        g_w_hi[o] = hi; g_w_lo[o] = lo;
    }
}

__global__ void prep_x(const float* __restrict__ x) {
    int t = blockIdx.x, b = blockIdx.y;
    int bg = b >> 6, r = b & 63;
    const float* src = x + ((size_t)b * Tlen + t) * Isz;
    size_t tbase = (((size_t)t * 2 + bg) * 8) * 8192;
    for (int k = threadIdx.x; k < Isz; k += blockDim.x) {
        float v = src[k];
        __nv_bfloat16 hi = __float2bfloat16(v);
        __nv_bfloat16 lo = __float2bfloat16(v - __bfloat162float(hi));
        int kt = k >> 6, kk = k & 63;
        size_t off = tbase + (size_t)kt * 8192 + r * 128 + (((kk * 2) ^ ((r & 7) << 4)));
        *(__nv_bfloat16*)(g_xs_hi + off) = hi;
        *(__nv_bfloat16*)(g_xs_lo + off) = lo;
    }
}

// ---------------- main persistent kernel ----------------
__global__ void __launch_bounds__(TPB, 1) lstm_mma(const float* __restrict__ bias,
                                                   float* __restrict__ out) {
    extern __shared__ char smem[];
    const uint32_t sbase = smem_u32(smem);
    float* bs = (float*)(smem + BS_OFF);

    const int tid = threadIdx.x, wid = tid >> 5, lid = tid & 31;
    const int cta = blockIdx.x;
    const int cg  = cta & 63;
    const int bg  = cta >> 6;
    const int mwarp = wid & 3, nwarp = wid >> 2;   // valid for wid<8

    // resident weight slice (one-time)
    for (int i = tid; i < 32 * 128 * 2; i += TPB) {
        int half = i >= 32 * 128;
        int j = half ? i - 32 * 128 : i;
        int c = j >> 7, ch = j & 127;
        int g = (c & 3) * 512 + cg * 8 + (c >> 2);
        const __nv_bfloat16* src = (half ? g_w_lo : g_w_hi) + (size_t)g * 1024 + ch * 8;
        cpa16(sbase + (half ? WS_LO : WS_HI) + c * WS_STRIDE + ch * 16, src);
    }
    CP_COMMIT();
    if (tid < 32)
        bs[tid] = bias[(tid & 3) * 512 + cg * 8 + (tid >> 2)];
    if (tid == 0) {
        #pragma unroll
        for (int s = 0; s < NSTG; s++) {
            mbar_init(sbase + MB_FULL  + s * 8, 1);
            mbar_init(sbase + MB_EMPTY + s * 8, 8);
        }
    }
    CP_WAIT(0);
    __syncthreads();

    // ---- producer tile issue (lane 0 of warp 8) ----
    auto issue_tile = [&](int t, int kt) {
        const int n = t * NKT + kt;
        const int s = n & 3;
        const uint32_t fullb  = sbase + MB_FULL  + s * 8;
        const uint32_t emptyb = sbase + MB_EMPTY + s * 8;
        mbar_wait(emptyb, ((n >> 2) & 1) ^ 1);
        const char *sh, *sl;
        if (kt < 8) {
            size_t o = (((size_t)t * 2 + bg) * 8 + kt) * 8192;
            sh = g_xs_hi + o; sl = g_xs_lo + o;
        } else {
            size_t o = (((size_t)(t & 1) * 2 + bg) * 8 + (kt - 8)) * 8192;
            sh = g_hs_hi + o; sl = g_hs_lo + o;
        }
        const uint32_t abuf = sbase + A_OFF + s * A_BUF;
        mbar_expect(fullb, 16384);
        bulk_ld(abuf,         sh, 8192, fullb);
        bulk_ld(abuf + A_LOH, sl, 8192, fullb);
    };

    // compute-warp fragment addressing
    const int rr = mwarp * 16 + (lid & 15);
    const uint32_t a_base  = rr * 128;
    const uint32_t a_cmask = (rr & 7) << 4;
    const uint32_t a_chi   = (lid >> 4) * 16;
    uint32_t bAddr[2][2];
    #pragma unroll
    for (int h = 0; h < 2; h++)
        #pragma unroll
        for (int nt = 0; nt < 2; nt++)
            bAddr[h][nt] = sbase + (h ? WS_LO : WS_HI)
                         + (nwarp * 16 + nt * 8 + (lid & 7)) * WS_STRIDE
                         + ((lid >> 3) & 1) * 16;

    float creg[2][2] = {{0.f, 0.f}, {0.f, 0.f}};

    // prime: x tiles 0..3 of step 0
    if (wid == 8 && lid == 0)
        for (int kt = 0; kt < 4; kt++) issue_tile(0, kt);

    for (int t = 0; t < Tlen; t++) {
        if (wid == 8) {
            // ---------------- producer warp ----------------
            if (lid == 0) {
                for (int kt = 4; kt < 8; kt++) issue_tile(t, kt);
                if (t > 0) {
                    while (g_release < (unsigned)t) { }
                    __threadfence();
                }
                for (int kt = 8; kt < NKT; kt++) issue_tile(t, kt);
                if (t + 1 < Tlen)
                    for (int kt = 0; kt < 4; kt++) issue_tile(t + 1, kt);
            }
        } else {
            // ---------------- compute warps ----------------
            float acc[2][4];
            #pragma unroll
            for (int nt = 0; nt < 2; nt++)
                #pragma unroll
                for (int j = 0; j < 4; j++) acc[nt][j] = 0.f;

            for (int kt = 0; kt < NKT; kt++) {
                const int n = t * NKT + kt;
                const int s = n & 3;
                mbar_wait(sbase + MB_FULL + s * 8, (n >> 2) & 1);

                const uint32_t abuf = sbase + A_OFF + s * A_BUF;
                #pragma unroll
                for (int ks = 0; ks < 4; ks++) {
                    uint32_t ah[4], al[4];
                    const uint32_t col = ((uint32_t)(ks * 32) + a_chi) ^ a_cmask;
                    LDSM4(ah, abuf + a_base + col);
                    LDSM4(al, abuf + A_LOH + a_base + col);
                    if (ks == 3 && lid == 0)
                        mbar_arrive(sbase + MB_EMPTY + s * 8);
                    const uint32_t koff = kt * 128 + ks * 32;
                    #pragma unroll
                    for (int nt = 0; nt < 2; nt++) {
                        uint32_t bh[2], bl[2];
                        LDSM2(bh, bAddr[0][nt] + koff);
                        LDSM2(bl, bAddr[1][nt] + koff);
                        MMA16816(acc[nt], ah, bh);
                        MMA16816(acc[nt], ah, bl);
                        MMA16816(acc[nt], al, bh);
                    }
                }
            }

            // ---- epilogue ----
            const int q = lid & 3;
            const int par2 = (t + 1) & 1;
            #pragma unroll
            for (int nt = 0; nt < 2; nt++) {
                const int s0 = nwarp * 16 + nt * 8 + q * 2;
                float d0 = acc[nt][0] + bs[s0];
                float d1 = acc[nt][1] + bs[s0 + 1];
                float d2 = acc[nt][2] + bs[s0];
                float d3 = acc[nt][3] + bs[s0 + 1];
                float e0 = __shfl_xor_sync(0xffffffffu, d0, 1);
                float e1 = __shfl_xor_sync(0xffffffffu, d1, 1);
                float e2 = __shfl_xor_sync(0xffffffffu, d2, 1);
                float e3 = __shfl_xor_sync(0xffffffffu, d3, 1);
                if (!(q & 1)) {
                    float i0 = sigmoidf_(d0), f0 = sigmoidf_(d1);
                    float g0 = tanhf(e0),     o0 = sigmoidf_(e1);
                    float c0 = tanhf(f0 * creg[nt][0] + i0 * g0);
                    float h0 = o0 * c0;  creg[nt][0] = c0;

                    float i1 = sigmoidf_(d2), f1 = sigmoidf_(d3);
                    float g1 = tanhf(e2),     o1 = sigmoidf_(e3);
                    float c1 = tanhf(f1 * creg[nt][1] + i1 * g1);
                    float h1 = o1 * c1;  creg[nt][1] = c1;

                    const int r    = lid >> 2;
                    const int b0i  = bg * 64 + mwarp * 16 + r;
                    const int hcol = cg * 8 + nwarp * 4 + nt * 2 + (q >> 1);
                    out[(size_t)b0i * (Tlen * Hsz) + (size_t)t * Hsz + hcol] = h0;
                    out[(size_t)(b0i + 8) * (Tlen * Hsz) + (size_t)t * Hsz + hcol] = h1;

                    const int kt2 = hcol >> 6, kk = hcol & 63;
                    __nv_bfloat16 hh0 = __float2bfloat16(h0);
                    __nv_bfloat16 hh1 = __float2bfloat16(h1);
                    {
                        int r0 = b0i & 63, bgh = b0i >> 6;
                        size_t off = (((size_t)par2 * 2 + bgh) * 8 + kt2) * 8192
                                   + r0 * 128 + (((kk * 2) ^ ((r0 & 7) << 4)));
                        *(__nv_bfloat16*)(g_hs_hi + off) = hh0;
                        *(__nv_bfloat16*)(g_hs_lo + off) =
                            __float2bfloat16(h0 - __bfloat162float(hh0));
                    }
                    {
                        int b1i = b0i + 8;
                        int r1 = b1i & 63, bgh = b1i >> 6;
                        size_t off = (((size_t)par2 * 2 + bgh) * 8 + kt2) * 8192
                                   + r1 * 128 + (((kk * 2) ^ ((r1 & 7) << 4)));
                        *(__nv_bfloat16*)(g_hs_hi + off) = hh1;
                        *(__nv_bfloat16*)(g_hs_lo + off) =
                            __float2bfloat16(h1 - __bfloat162float(hh1));
                    }
                }
            }
            __threadfence();   // publish h stores before the flag
        }

        // one CTA-wide sync per step, then producer warp runs the grid barrier
        __syncthreads();
        if (t < Tlen - 1 && wid == 8) {
            unsigned gen = (unsigned)(t + 1);
            if (cta == 0) {
                if (lid == 0) g_flags[0] = gen;
                bool done;
                do {
                    done = true;
                    #pragma unroll
                    for (int j = 0; j < NCTA / 32; j++)
                        if (g_flags[lid + 32 * j] < gen) done = false;
                } while (!__all_sync(0xffffffffu, done));
                if (lid == 0) { __threadfence(); g_release = gen; }
            } else if (lid == 0) {
                g_flags[cta] = gen;
            }
        }
    }
}

// ---------------- launch ----------------
extern "C" void kernel_launch(void* const* d_in, const int* in_sizes, int n_in,
                              void* d_out, int out_size) {
    const float* x    = (const float*)d_in[0];
    const float* Wk   = (const float*)d_in[1];
    const float* Rk   = (const float*)d_in[2];
    const float* bias = (const float*)d_in[3];
    float* out = (float*)d_out;

    cudaFuncSetAttribute(lstm_mma, cudaFuncAttributeMaxDynamicSharedMemorySize, SMEM_TOTAL);

    init_kernel<<<64, PTPB>>>();
    prep_w<<<dim3(64, 32), PTPB>>>(Wk, Rk);
    prep_x<<<dim3(Tlen, Bsz), 128>>>(x);
    lstm_mma<<<NCTA, TPB, SMEM_TOTAL>>>(bias, out);
}